// round 5
// baseline (speedup 1.0000x reference)
#include <cuda_runtime.h>
#include <math.h>

#define B_ROWS    8192
#define DIM       768
#define NE        8
#define TPB       192              // 768 / 4 = 192 float4 per row
#define NWARP     (TPB / 32)

// Deterministic cross-block accumulators (integer => order-independent).
// Zero-initialized at module load; last block self-resets them each launch,
// so every graph replay starts from a clean state.
__device__ unsigned long long g_soft_fx[NE];   // sum of gs * 2^32
__device__ int                g_hard_cnt[NE];  // count of gs >= 1e-5
__device__ unsigned int       g_arrive;        // block arrival counter

#define FX_SCALE 4294967296.0                  // 2^32

__global__ __launch_bounds__(TPB)
void moe_gate_mix_kernel(const float* __restrict__ h,
                         const float* __restrict__ x,
                         const float* __restrict__ W,
                         const float* __restrict__ bias,
                         float* __restrict__ y,
                         float* __restrict__ stats_out)
{
    const int row  = blockIdx.x;
    const int t    = threadIdx.x;
    const int warp = t >> 5;
    const int lane = t & 31;

    __shared__ float s_red[NWARP][NE];
    __shared__ float s_gs[NE];

    // ---------- Issue ALL h loads first (latency overlaps the gate stage) ----
    // Thread t owns d = t + 192k: lanes consecutive -> each LDG.128 covers a
    // contiguous 512B warp footprint. .cs = streaming (evict-first in L2).
    const float4* h4 = reinterpret_cast<const float4*>(h + (size_t)row * DIM * NE);
    float4 va[4], vb[4];
#pragma unroll
    for (int k = 0; k < 4; k++) {
        const int d = t + TPB * k;
        va[k] = __ldcs(&h4[2 * d + 0]);
        vb[k] = __ldcs(&h4[2 * d + 1]);
    }

    // ---------- Stage 1: gate logits = x[row] @ W^T + b ----------
    const float4* x4 = reinterpret_cast<const float4*>(x + (size_t)row * DIM);
    const float4  xv = __ldcs(&x4[t]);

    float part[NE];
#pragma unroll
    for (int e = 0; e < NE; e++) {
        const float4* w4 = reinterpret_cast<const float4*>(W + e * DIM);
        const float4  wv = __ldg(&w4[t]);          // 24KB, L2/L1-resident
        part[e] = xv.x * wv.x + xv.y * wv.y + xv.z * wv.z + xv.w * wv.w;
    }
#pragma unroll
    for (int e = 0; e < NE; e++) {
        float v = part[e];
#pragma unroll
        for (int o = 16; o > 0; o >>= 1)
            v += __shfl_xor_sync(0xffffffffu, v, o);
        part[e] = v;
    }
    if (lane == 0) {
#pragma unroll
        for (int e = 0; e < NE; e++) s_red[warp][e] = part[e];
    }
    __syncthreads();

    if (t == 0) {
        float lg[NE];
#pragma unroll
        for (int e = 0; e < NE; e++) {
            float v = bias[e];
#pragma unroll
            for (int w = 0; w < NWARP; w++) v += s_red[w][e];
            lg[e] = v;                              // TAU = 1.0
        }
        float m = lg[0];
#pragma unroll
        for (int e = 1; e < NE; e++) m = fmaxf(m, lg[e]);
        float ex[NE], s = 0.f;
#pragma unroll
        for (int e = 0; e < NE; e++) { ex[e] = __expf(lg[e] - m); s += ex[e]; }
        const float inv_s = 1.f / s;

        int i0 = 0;
#pragma unroll
        for (int e = 1; e < NE; e++) if (lg[e] > lg[i0]) i0 = e;
        int i1 = (i0 == 0) ? 1 : 0;
#pragma unroll
        for (int e = 0; e < NE; e++) if (e != i0 && lg[e] > lg[i1]) i1 = e;

        const float g0 = ex[i0] * inv_s;
        const float g1 = ex[i1] * inv_s;
        const float a0 = lg[i0] - logf(fmaxf(2.f * (g0 + 1e-10f), 1e-10f));
        const float a1 = lg[i1] - logf(fmaxf(2.f * (g1 + 1e-10f), 1e-10f));
        const float am = fmaxf(a0, a1);
        const float e0 = expf(a0 - am);
        const float e1 = expf(a1 - am);
        const float ri = 1.f / (e0 + e1);
        const float w0 = e0 * ri;
        const float w1 = e1 * ri;

#pragma unroll
        for (int e = 0; e < NE; e++) s_gs[e] = 0.f;
        s_gs[i0] = w0;
        s_gs[i1] = w1;

        // ---- deterministic stats: integer atomics (order-independent) ----
        atomicAdd(&g_soft_fx[i0], (unsigned long long)((double)w0 * FX_SCALE));
        atomicAdd(&g_soft_fx[i1], (unsigned long long)((double)w1 * FX_SCALE));
        if (!(w0 < 1e-5f)) atomicAdd(&g_hard_cnt[i0], 1);
        if (!(w1 < 1e-5f)) atomicAdd(&g_hard_cnt[i1], 1);
    }
    __syncthreads();

    float gs[NE];
#pragma unroll
    for (int e = 0; e < NE; e++) gs[e] = s_gs[e];

    // ---------- Stage 2: y[row, d] = sum_e h[row, d, e] * gs[e] ----------
    float* yrow = y + (size_t)row * DIM;
#pragma unroll
    for (int k = 0; k < 4; k++) {
        const int d = t + TPB * k;
        const float4 a = va[k];
        const float4 c = vb[k];
        __stcs(&yrow[d],
               a.x * gs[0] + a.y * gs[1] + a.z * gs[2] + a.w * gs[3]
             + c.x * gs[4] + c.y * gs[5] + c.z * gs[6] + c.w * gs[7]);
    }

    // ---------- Last block finalizes stats and resets globals ----------
    if (t == 0) {
        __threadfence();
        const unsigned int prev = atomicAdd(&g_arrive, 1u);
        if (prev == (unsigned int)(gridDim.x - 1)) {
            const double invB  = 1.0 / (double)B_ROWS;
            const double invFx = 1.0 / FX_SCALE;
#pragma unroll
            for (int e = 0; e < NE; e++) {
                const unsigned long long sfx = g_soft_fx[e];
                const int                hc  = g_hard_cnt[e];
                stats_out[e]      = (float)((double)sfx * invFx * invB);
                stats_out[NE + e] = (float)((double)hc * invB);
                g_soft_fx[e]  = 0ull;               // self-reset for next replay
                g_hard_cnt[e] = 0;
            }
            g_arrive = 0u;
            __threadfence();
        }
    }
}

extern "C" void kernel_launch(void* const* d_in, const int* in_sizes, int n_in,
                              void* d_out, int out_size)
{
    const float* h    = (const float*)d_in[0];   // (8192, 768, 8)
    const float* x    = (const float*)d_in[1];   // (8192, 768)
    const float* W    = (const float*)d_in[2];   // (8, 768)
    const float* bias = (const float*)d_in[3];   // (8,)
    float* out = (float*)d_out;

    moe_gate_mix_kernel<<<B_ROWS, TPB>>>(h, x, W, bias, out,
                                         out + (size_t)B_ROWS * DIM);
}